// round 14
// baseline (speedup 1.0000x reference)
#include <cuda_runtime.h>
#include <cuda_fp16.h>
#include <cstdint>
#include <cstddef>

// ---------------- problem constants ----------------
#define NB      65536

// padded k-strides (fp16 elems)
#define KP1 136                // k=128 tiles (rows 272B)
#define KPX 264                // k_l2 X tile k=256 (rows 528B)
#define KPW 72                 // k_l2 W chunk k=64 (rows 144B)

// ---------------- smem layouts ----------------
#define SM1_VEC 0
#define SM1_XF  1024
#define SM1_WH  (SM1_XF + 34816)                // W1 half [128][136]
#define SM1_WL  (SM1_WH + 34816)
#define SMEM_L1 (SM1_WL + 34816)                // 105472 B -> 2 CTAs/SM

#define SM2_VEC 0
#define SM2_XF  2048                            // [128][264] fp16 = 67584
#define SM2_WH  (SM2_XF + 67584)                // W2 half k-chunk [128][72] = 18432
#define SM2_WL  (SM2_WH + 18432)
#define SMEM_L2 (SM2_WL + 18432)                // 106496 B -> 2 CTAs/SM

// ---------------- device scratch ----------------
__device__ __align__(16) uint32_t g_xf32[(size_t)NB * 64];    // X fp16 [B][128]
__device__ __align__(16) uint32_t g_x1f32[(size_t)NB * 128];  // x1 fp16 [B][256]
__device__ __align__(16) uint32_t g_w1h32[256 * 64];          // W1 hi fp16 [256][128]
__device__ __align__(16) uint32_t g_w1l32[256 * 64];          // W1 lo fp16
__device__ __align__(16) uint32_t g_w2h32[256 * 128];         // W2 hi fp16 [256][256]
__device__ __align__(16) uint32_t g_w2l32[256 * 128];         // W2 lo fp16
__device__ float g_wc[256];
__device__ float g_bc;

// ---------------- PTX helpers ----------------
__device__ __forceinline__ uint32_t smem_u32(const void* p) {
    uint32_t a;
    asm("{ .reg .u64 t; cvta.to.shared.u64 t, %1; cvt.u32.u64 %0, t; }" : "=r"(a) : "l"(p));
    return a;
}
__device__ __forceinline__ void cp16(uint32_t dst, const void* src) {
    asm volatile("cp.async.cg.shared.global [%0], [%1], 16;" :: "r"(dst), "l"(src));
}
#define CP_COMMIT() asm volatile("cp.async.commit_group;")
#define CP_WAIT0()  asm volatile("cp.async.wait_group 0;" ::: "memory")
#define CP_WAIT1()  asm volatile("cp.async.wait_group 1;" ::: "memory")

__device__ __forceinline__ void ldsm4(uint32_t* r, uint32_t addr) {
    asm volatile("ldmatrix.sync.aligned.m8n8.x4.shared.b16 {%0,%1,%2,%3}, [%4];"
        : "=r"(r[0]), "=r"(r[1]), "=r"(r[2]), "=r"(r[3]) : "r"(addr));
}
__device__ __forceinline__ void mma_f16(float* c, const uint32_t* a, const uint32_t* b) {
    asm volatile(
        "mma.sync.aligned.m16n8k16.row.col.f32.f16.f16.f32 "
        "{%0,%1,%2,%3},{%4,%5,%6,%7},{%8,%9},{%0,%1,%2,%3};"
        : "+f"(c[0]), "+f"(c[1]), "+f"(c[2]), "+f"(c[3])
        : "r"(a[0]), "r"(a[1]), "r"(a[2]), "r"(a[3]), "r"(b[0]), "r"(b[1]));
}
// exact fp16 split of two fp32 weights: hi pair + residual-lo pair
__device__ __forceinline__ void splitw2(float v0, float v1, uint32_t& hi, uint32_t& lo) {
    __half h0 = __float2half_rn(v0), h1 = __float2half_rn(v1);
    __half l0 = __float2half_rn(v0 - __half2float(h0));
    __half l1 = __float2half_rn(v1 - __half2float(h1));
    hi = (uint32_t)__half_as_ushort(h0) | ((uint32_t)__half_as_ushort(h1) << 16);
    lo = (uint32_t)__half_as_ushort(l0) | ((uint32_t)__half_as_ushort(l1) << 16);
}
__device__ __forceinline__ uint32_t cvt2h(float v0, float v1) {
    __half2 h = __floats2half2_rn(v0, v1);
    return *reinterpret_cast<uint32_t*>(&h);
}

// one pass over KS k-steps: warp tile 64x32 -> 4 A-ldsm + 2 B-ldsm + 16 mma per step
template<int KS>
__device__ __forceinline__ void gemm_pass(float acc[4][4][4], uint32_t Ab, uint32_t Bb,
                                          int kpA, int kpW) {
    #pragma unroll
    for (int ks = 0; ks < KS; ks++) {
        uint32_t a[4][4], b[2][4];
        #pragma unroll
        for (int mi = 0; mi < 4; mi++) ldsm4(a[mi], Ab + (mi * 16 * kpA + ks * 16) * 2);
        ldsm4(b[0], Bb + (ks * 16) * 2);
        ldsm4(b[1], Bb + (16 * kpW + ks * 16) * 2);
        #pragma unroll
        for (int mi = 0; mi < 4; mi++) {
            mma_f16(acc[mi][0], a[mi], &b[0][0]);
            mma_f16(acc[mi][1], a[mi], &b[0][2]);
            mma_f16(acc[mi][2], a[mi], &b[1][0]);
            mma_f16(acc[mi][3], a[mi], &b[1][2]);
        }
    }
}

// ---------------- prep: weight splits (parallel) ----------------
__global__ void k_prep_w(const float* __restrict__ W1, const float* __restrict__ W2) {
    int bid = blockIdx.x, tid = threadIdx.x;
    if (bid < 64) {
        int i = bid * 256 + tid;
        int row = i >> 6, kp = i & 63;
        splitw2(W1[row * 128 + kp * 2], W1[row * 128 + kp * 2 + 1], g_w1h32[i], g_w1l32[i]);
    } else {
        int j = (bid - 64) * 256 + tid;
        int row = j >> 7, kp = j & 127;
        splitw2(W2[row * 256 + kp * 2], W2[row * 256 + kp * 2 + 1], g_w2h32[j], g_w2l32[j]);
    }
}

// ---------------- prep: head collapse, parallel over k ----------------
__global__ void k_prep_head(const float* __restrict__ alphas,
                            const float* __restrict__ Wh, const float* __restrict__ bh) {
    __shared__ float red[256];
    const int t = threadIdx.x, k = blockIdx.x;
    red[t] = (t < 200) ? alphas[t] * Wh[t * 256 + k] : 0.0f;
    __syncthreads();
    #pragma unroll
    for (int s = 128; s > 0; s >>= 1) {
        if (t < s) red[t] += red[t + s];
        __syncthreads();
    }
    if (t == 0) g_wc[k] = red[0];
    if (k == 0) {
        __syncthreads();
        red[t] = (t < 200) ? alphas[t] * bh[t] : 0.0f;
        __syncthreads();
        #pragma unroll
        for (int s = 128; s > 0; s >>= 1) {
            if (t < s) red[t] += red[t + s];
            __syncthreads();
        }
        if (t == 0) g_bc = red[0];
    }
}

// ---------------- prep: X -> fp16 plane (vectorized) + zero out ----------------
__global__ void k_prepx(const float* __restrict__ state, const float* __restrict__ action,
                        float* __restrict__ out) {
    int gid = blockIdx.x * blockDim.x + threadIdx.x;   // 1,048,576 = NB*16
    if (gid < NB) out[gid] = 0.0f;                     // fold k_zero
    int b  = gid >> 4;
    int kq = gid & 15;                                 // which 8-elem group of 128
    const float* src = (kq < 12) ? state + (size_t)b * 96 + kq * 8
                                 : action + (size_t)b * 32 + (kq - 12) * 8;
    float4 v0 = *(const float4*)src;
    float4 v1 = *(const float4*)(src + 4);
    uint4 o;
    o.x = cvt2h(v0.x, v0.y);  o.y = cvt2h(v0.z, v0.w);
    o.z = cvt2h(v1.x, v1.y);  o.w = cvt2h(v1.z, v1.w);
    *(uint4*)(g_xf32 + (size_t)b * 64 + kq * 4) = o;
}

// ---------------- layer 1 (PERSISTENT): x1 = relu(X @ W1^T + b1) -> fp16 plane ----------------
// grid 296 = 148 SMs x 2 CTAs; each CTA pins its nh's W1-half and loops row-tiles
__global__ __launch_bounds__(256, 2)
void k_l1(const float* __restrict__ b1)
{
    extern __shared__ char smem[];
    const uint32_t sb = smem_u32(smem);
    const int tid = threadIdx.x;
    const int nh  = blockIdx.x & 1;
    const int c0  = blockIdx.x >> 1;          // 0..147

    // W1-half hi + lo planes, loaded ONCE
    for (int i = tid; i < 2048; i += 256) {
        int r = i >> 4, c = i & 15;
        cp16(sb + SM1_WH + r * 272 + c * 16, g_w1h32 + (size_t)(nh * 128 + r) * 64 + c * 4);
        cp16(sb + SM1_WL + r * 272 + c * 16, g_w1l32 + (size_t)(nh * 128 + r) * 64 + c * 4);
    }
    CP_COMMIT();

    float* b1s = (float*)(smem + SM1_VEC);
    if (tid < 128) b1s[tid] = b1[nh * 128 + tid];

    const int wid = tid >> 5, lane = tid & 31;
    const int wm = (wid & 1) * 64, wn = (wid >> 1) * 32;
    const int g = lane >> 2, tg = lane & 3;
    const uint32_t aF = sb + SM1_XF + (((uint32_t)(wm + (lane & 15))) * KP1 + ((lane >> 4) * 8)) * 2;
    const uint32_t bH = sb + SM1_WH + (((uint32_t)(wn + (lane & 7) + ((lane >> 4) * 8))) * KP1
                                        + (((lane >> 3) & 1) * 8)) * 2;
    const uint32_t bL = sb + SM1_WL + (((uint32_t)(wn + (lane & 7) + ((lane >> 4) * 8))) * KP1
                                        + (((lane >> 3) & 1) * 8)) * 2;

    CP_WAIT0();               // W resident
    __syncthreads();

    for (int t = c0; t < 512; t += 148) {
        const int row0 = t * 128;

        // X tile load (buffer free: either first iter or post-sync below)
        for (int i = tid; i < 2048; i += 256) {
            int r = i >> 4, c = i & 15;
            cp16(sb + SM1_XF + r * 272 + c * 16, g_xf32 + (size_t)(row0 + r) * 64 + c * 4);
        }
        CP_COMMIT(); CP_WAIT0();
        __syncthreads();

        float acc[4][4][4];
        #pragma unroll
        for (int i = 0; i < 4; i++)
            #pragma unroll
            for (int j = 0; j < 4; j++)
                #pragma unroll
                for (int c = 0; c < 4; c++) acc[i][j][c] = 0.0f;

        gemm_pass<8>(acc, aF, bH, KP1, KP1);   // Xf * Wh
        gemm_pass<8>(acc, aF, bL, KP1, KP1);   // Xf * Wl

        // epilogue: bias + relu -> fp16, packed pair stores to x1 plane
        #pragma unroll
        for (int mi = 0; mi < 4; mi++) {
            #pragma unroll
            for (int nj = 0; nj < 4; nj++) {
                int rA = row0 + wm + mi * 16 + g;
                int colL = wn + nj * 8 + tg * 2;
                float v0 = fmaxf(acc[mi][nj][0] + b1s[colL],     0.0f);
                float v1 = fmaxf(acc[mi][nj][1] + b1s[colL + 1], 0.0f);
                float v2 = fmaxf(acc[mi][nj][2] + b1s[colL],     0.0f);
                float v3 = fmaxf(acc[mi][nj][3] + b1s[colL + 1], 0.0f);
                size_t ix = (size_t)rA * 128 + nh * 64 + (colL >> 1);
                g_x1f32[ix]           = cvt2h(v0, v1);
                g_x1f32[ix + 8 * 128] = cvt2h(v2, v3);
            }
        }
        __syncthreads();    // all warps done reading X before next overwrite
    }
}

// ---------------- layer 2 + head fused, writes out directly ----------------
// 256 threads, 8 warps of 64x32, N-half per CTA, K chunked 4x64, 2 CTAs/SM
__global__ __launch_bounds__(256, 2)
void k_l2(const float* __restrict__ b2, float* __restrict__ out)
{
    extern __shared__ char smem[];
    const uint32_t sb = smem_u32(smem);
    const int tid  = threadIdx.x;
    const int half = blockIdx.x & 1;
    const int row0 = (blockIdx.x >> 1) * 128;

    float* b2s   = (float*)(smem + SM2_VEC);   // [128]
    float* wcs   = b2s + 128;                  // [128]
    float* stage = wcs + 128;                  // [128]
    if (tid < 128) {
        b2s[tid]   = b2[half * 128 + tid];
        wcs[tid]   = g_wc[half * 128 + tid];
        stage[tid] = 0.0f;
    }

    // group 0: X plane fp16 [128][256]
    for (int i = tid; i < 4096; i += 256) {
        int r = i >> 5, c = i & 31;
        cp16(sb + SM2_XF + r * 528 + c * 16, g_x1f32 + (size_t)(row0 + r) * 128 + c * 4);
    }
    CP_COMMIT();
    // W chunk 0 (k=0..63): hi group, lo group
    for (int i = tid; i < 1024; i += 256) {
        int r = i >> 3, c = i & 7;
        cp16(sb + SM2_WH + r * 144 + c * 16, g_w2h32 + (size_t)(half * 128 + r) * 128 + c * 4);
    }
    CP_COMMIT();
    for (int i = tid; i < 1024; i += 256) {
        int r = i >> 3, c = i & 7;
        cp16(sb + SM2_WL + r * 144 + c * 16, g_w2l32 + (size_t)(half * 128 + r) * 128 + c * 4);
    }
    CP_COMMIT();

    const int wid = tid >> 5, lane = tid & 31;
    const int wm = (wid & 1) * 64, wn = (wid >> 1) * 32;
    const int g = lane >> 2, tg = lane & 3;
    const uint32_t aF = sb + SM2_XF + (((uint32_t)(wm + (lane & 15))) * KPX + ((lane >> 4) * 8)) * 2;
    const uint32_t bH = sb + SM2_WH + (((uint32_t)(wn + (lane & 7) + ((lane >> 4) * 8))) * KPW
                                        + (((lane >> 3) & 1) * 8)) * 2;
    const uint32_t bL = sb + SM2_WL + (((uint32_t)(wn + (lane & 7) + ((lane >> 4) * 8))) * KPW
                                        + (((lane >> 3) & 1) * 8)) * 2;

    float acc[4][4][4];
    #pragma unroll
    for (int i = 0; i < 4; i++)
        #pragma unroll
        for (int j = 0; j < 4; j++)
            #pragma unroll
            for (int c = 0; c < 4; c++) acc[i][j][c] = 0.0f;

    #pragma unroll 1
    for (int kc = 0; kc < 4; kc++) {             // K chunks of 64
        const uint32_t ao = (uint32_t)kc * 128;  // 64 elems * 2B

        CP_WAIT1();                 // current Wh (and X on first iter) ready
        __syncthreads();
        gemm_pass<4>(acc, aF + ao, bH, KPX, KPW);   // Xf * Wh
        __syncthreads();            // all warps done with Wh buffer
        if (kc < 3) {               // prefetch next chunk's Wh
            for (int i = tid; i < 1024; i += 256) {
                int r = i >> 3, cc = i & 7;
                cp16(sb + SM2_WH + r * 144 + cc * 16,
                     g_w2h32 + (size_t)(half * 128 + r) * 128 + (kc + 1) * 32 + cc * 4);
            }
            CP_COMMIT();
            CP_WAIT1();             // current Wl ready (next Wh may pend)
        } else {
            CP_WAIT0();
        }
        __syncthreads();
        gemm_pass<4>(acc, aF + ao, bL, KPX, KPW);   // Xf * Wl
        __syncthreads();            // all warps done with Wl buffer
        if (kc < 3) {               // prefetch next chunk's Wl
            for (int i = tid; i < 1024; i += 256) {
                int r = i >> 3, cc = i & 7;
                cp16(sb + SM2_WL + r * 144 + cc * 16,
                     g_w2l32 + (size_t)(half * 128 + r) * 128 + (kc + 1) * 32 + cc * 4);
            }
            CP_COMMIT();
        }
    }

    // fused epilogue: bias + relu + head dot -> per-row scalar
    float rs[4][2];
    #pragma unroll
    for (int mi = 0; mi < 4; mi++) { rs[mi][0] = 0.0f; rs[mi][1] = 0.0f; }
    #pragma unroll
    for (int mi = 0; mi < 4; mi++) {
        #pragma unroll
        for (int nj = 0; nj < 4; nj++) {
            int n0 = wn + nj * 8 + tg * 2;
            float w0 = wcs[n0], w1 = wcs[n0 + 1];
            float bb0 = b2s[n0], bb1 = b2s[n0 + 1];
            rs[mi][0] += fmaxf(acc[mi][nj][0] + bb0, 0.0f) * w0
                       + fmaxf(acc[mi][nj][1] + bb1, 0.0f) * w1;
            rs[mi][1] += fmaxf(acc[mi][nj][2] + bb0, 0.0f) * w0
                       + fmaxf(acc[mi][nj][3] + bb1, 0.0f) * w1;
        }
    }
    #pragma unroll
    for (int mi = 0; mi < 4; mi++) {
        #pragma unroll
        for (int rb = 0; rb < 2; rb++) {
            float s = rs[mi][rb];
            s += __shfl_xor_sync(0xFFFFFFFFu, s, 1);
            s += __shfl_xor_sync(0xFFFFFFFFu, s, 2);
            if (tg == 0) atomicAdd(&stage[wm + mi * 16 + g + rb * 8], s);
        }
    }
    __syncthreads();
    // both N-halves accumulate into out[row] (out zeroed by k_prepx)
    if (tid < 128) atomicAdd(&out[row0 + tid], stage[tid] + 0.5f * g_bc);
}

// ---------------- launch ----------------
extern "C" void kernel_launch(void* const* d_in, const int* in_sizes, int n_in,
                              void* d_out, int out_size) {
    const float* state  = (const float*)d_in[0];
    const float* action = (const float*)d_in[1];
    const float* alphas = (const float*)d_in[2];
    const float* W1     = (const float*)d_in[3];
    const float* b1     = (const float*)d_in[4];
    const float* W2     = (const float*)d_in[5];
    const float* b2     = (const float*)d_in[6];
    const float* Wh     = (const float*)d_in[7];
    const float* bh     = (const float*)d_in[8];
    float* out = (float*)d_out;

    cudaFuncSetAttribute(k_l1, cudaFuncAttributeMaxDynamicSharedMemorySize, SMEM_L1);
    cudaFuncSetAttribute(k_l2, cudaFuncAttributeMaxDynamicSharedMemorySize, SMEM_L2);

    k_prep_w<<<192, 256>>>(W1, W2);
    k_prep_head<<<256, 256>>>(alphas, Wh, bh);
    k_prepx<<<4096, 256>>>(state, action, out);
    k_l1<<<296, 256, SMEM_L1>>>(b1);
    k_l2<<<1024, 256, SMEM_L2>>>(b2, out);
}

// round 15
// speedup vs baseline: 1.3183x; 1.3183x over previous
#include <cuda_runtime.h>
#include <cuda_fp16.h>
#include <cstdint>
#include <cstddef>

// ---------------- problem constants ----------------
#define NB      65536

// padded k-strides (fp16 elems)
#define KP1 136                // k=128 tiles (rows 272B)
#define KPX 264                // k_l2 X tile k=256 (rows 528B)
#define KPW 72                 // k_l2 W chunk k=64 (rows 144B)

// ---------------- smem layouts ----------------
#define SM1_VEC 0
#define SM1_XF  1024
#define SM1_WH  (SM1_XF + 34816)                // W1 half [128][136]
#define SM1_WL  (SM1_WH + 34816)
#define SMEM_L1 (SM1_WL + 34816)                // 105472 B -> 2 CTAs/SM

#define SM2_VEC 0
#define SM2_XF  2048                            // [128][264] fp16 = 67584
#define SM2_WH  (SM2_XF + 67584)                // W2 half k-chunk [128][72] = 18432
#define SM2_WL  (SM2_WH + 18432)
#define SMEM_L2 (SM2_WL + 18432)                // 106496 B -> 2 CTAs/SM

// ---------------- device scratch ----------------
__device__ __align__(16) uint32_t g_xf32[(size_t)NB * 64];    // X fp16 [B][128]
__device__ __align__(16) uint32_t g_x1f32[(size_t)NB * 128];  // x1 fp16 [B][256]
__device__ __align__(16) uint32_t g_w1h32[256 * 64];          // W1 hi fp16 [256][128]
__device__ __align__(16) uint32_t g_w1l32[256 * 64];          // W1 lo fp16
__device__ __align__(16) uint32_t g_w2h32[256 * 128];         // W2 hi fp16 [256][256]
__device__ __align__(16) uint32_t g_w2l32[256 * 128];         // W2 lo fp16
__device__ float g_wc[256];
__device__ float g_bc;

// ---------------- PTX helpers ----------------
__device__ __forceinline__ uint32_t smem_u32(const void* p) {
    uint32_t a;
    asm("{ .reg .u64 t; cvta.to.shared.u64 t, %1; cvt.u32.u64 %0, t; }" : "=r"(a) : "l"(p));
    return a;
}
__device__ __forceinline__ void cp16(uint32_t dst, const void* src) {
    asm volatile("cp.async.cg.shared.global [%0], [%1], 16;" :: "r"(dst), "l"(src));
}
#define CP_COMMIT() asm volatile("cp.async.commit_group;")
#define CP_WAIT0()  asm volatile("cp.async.wait_group 0;" ::: "memory")
#define CP_WAIT1()  asm volatile("cp.async.wait_group 1;" ::: "memory")

__device__ __forceinline__ void ldsm4(uint32_t* r, uint32_t addr) {
    asm volatile("ldmatrix.sync.aligned.m8n8.x4.shared.b16 {%0,%1,%2,%3}, [%4];"
        : "=r"(r[0]), "=r"(r[1]), "=r"(r[2]), "=r"(r[3]) : "r"(addr));
}
__device__ __forceinline__ void mma_f16(float* c, const uint32_t* a, const uint32_t* b) {
    asm volatile(
        "mma.sync.aligned.m16n8k16.row.col.f32.f16.f16.f32 "
        "{%0,%1,%2,%3},{%4,%5,%6,%7},{%8,%9},{%0,%1,%2,%3};"
        : "+f"(c[0]), "+f"(c[1]), "+f"(c[2]), "+f"(c[3])
        : "r"(a[0]), "r"(a[1]), "r"(a[2]), "r"(a[3]), "r"(b[0]), "r"(b[1]));
}
// exact fp16 split of two fp32 weights: hi pair + residual-lo pair
__device__ __forceinline__ void splitw2(float v0, float v1, uint32_t& hi, uint32_t& lo) {
    __half h0 = __float2half_rn(v0), h1 = __float2half_rn(v1);
    __half l0 = __float2half_rn(v0 - __half2float(h0));
    __half l1 = __float2half_rn(v1 - __half2float(h1));
    hi = (uint32_t)__half_as_ushort(h0) | ((uint32_t)__half_as_ushort(h1) << 16);
    lo = (uint32_t)__half_as_ushort(l0) | ((uint32_t)__half_as_ushort(l1) << 16);
}
__device__ __forceinline__ uint32_t cvt2h(float v0, float v1) {
    __half2 h = __floats2half2_rn(v0, v1);
    return *reinterpret_cast<uint32_t*>(&h);
}

// one pass over KS k-steps: warp tile 64x32 -> 4 A-ldsm + 2 B-ldsm + 16 mma per step
template<int KS>
__device__ __forceinline__ void gemm_pass(float acc[4][4][4], uint32_t Ab, uint32_t Bb,
                                          int kpA, int kpW) {
    #pragma unroll
    for (int ks = 0; ks < KS; ks++) {
        uint32_t a[4][4], b[2][4];
        #pragma unroll
        for (int mi = 0; mi < 4; mi++) ldsm4(a[mi], Ab + (mi * 16 * kpA + ks * 16) * 2);
        ldsm4(b[0], Bb + (ks * 16) * 2);
        ldsm4(b[1], Bb + (16 * kpW + ks * 16) * 2);
        #pragma unroll
        for (int mi = 0; mi < 4; mi++) {
            mma_f16(acc[mi][0], a[mi], &b[0][0]);
            mma_f16(acc[mi][1], a[mi], &b[0][2]);
            mma_f16(acc[mi][2], a[mi], &b[1][0]);
            mma_f16(acc[mi][3], a[mi], &b[1][2]);
        }
    }
}

// ---------------- unified prep: W splits + head collapse + X convert + out zero ----------------
// blocks 0..191: weight splits; 192..447: head collapse; 448..4543: X convert
__global__ void k_prep(const float* __restrict__ W1, const float* __restrict__ W2,
                       const float* __restrict__ alphas, const float* __restrict__ Wh,
                       const float* __restrict__ bh,
                       const float* __restrict__ state, const float* __restrict__ action,
                       float* __restrict__ out) {
    const int bid = blockIdx.x, tid = threadIdx.x;
    if (bid < 64) {                       // W1 split
        int i = bid * 256 + tid;
        int row = i >> 6, kp = i & 63;
        splitw2(W1[row * 128 + kp * 2], W1[row * 128 + kp * 2 + 1], g_w1h32[i], g_w1l32[i]);
    } else if (bid < 192) {               // W2 split
        int j = (bid - 64) * 256 + tid;
        int row = j >> 7, kp = j & 127;
        splitw2(W2[row * 256 + kp * 2], W2[row * 256 + kp * 2 + 1], g_w2h32[j], g_w2l32[j]);
    } else if (bid < 448) {               // head collapse (one k per block)
        __shared__ float red[256];
        const int k = bid - 192;
        red[tid] = (tid < 200) ? alphas[tid] * Wh[tid * 256 + k] : 0.0f;
        __syncthreads();
        #pragma unroll
        for (int s = 128; s > 0; s >>= 1) {
            if (tid < s) red[tid] += red[tid + s];
            __syncthreads();
        }
        if (tid == 0) g_wc[k] = red[0];
        if (k == 0) {
            __syncthreads();
            red[tid] = (tid < 200) ? alphas[tid] * bh[tid] : 0.0f;
            __syncthreads();
            #pragma unroll
            for (int s = 128; s > 0; s >>= 1) {
                if (tid < s) red[tid] += red[tid + s];
                __syncthreads();
            }
            if (tid == 0) g_bc = red[0];
        }
    } else {                              // X convert + zero out
        int gid = (bid - 448) * 256 + tid;     // 0 .. NB*16-1
        if (gid < NB) out[gid] = 0.0f;
        int b  = gid >> 4;
        int kq = gid & 15;
        const float* src = (kq < 12) ? state + (size_t)b * 96 + kq * 8
                                     : action + (size_t)b * 32 + (kq - 12) * 8;
        float4 v0 = *(const float4*)src;
        float4 v1 = *(const float4*)(src + 4);
        uint4 o;
        o.x = cvt2h(v0.x, v0.y);  o.y = cvt2h(v0.z, v0.w);
        o.z = cvt2h(v1.x, v1.y);  o.w = cvt2h(v1.z, v1.w);
        *(uint4*)(g_xf32 + (size_t)b * 64 + kq * 4) = o;
    }
}

// ---------------- layer 1: x1 = relu(X @ W1^T + b1) -> fp16 plane (R12 config) ----------------
// 256 threads, 8 warps of 64x32, CTA tile 128(m) x 128(n-half); 2 CTAs/SM, grid 1024
__global__ __launch_bounds__(256, 2)
void k_l1(const float* __restrict__ b1)
{
    extern __shared__ char smem[];
    const uint32_t sb = smem_u32(smem);
    const int tid = threadIdx.x;
    const int nh  = blockIdx.x & 1;
    const int row0 = (blockIdx.x >> 1) * 128;

    // group 0: X plane fp16 [128][128]
    for (int i = tid; i < 2048; i += 256) {
        int r = i >> 4, c = i & 15;
        cp16(sb + SM1_XF + r * 272 + c * 16, g_xf32 + (size_t)(row0 + r) * 64 + c * 4);
    }
    CP_COMMIT();
    // group 1: W1-half hi plane
    for (int i = tid; i < 2048; i += 256) {
        int r = i >> 4, c = i & 15;
        cp16(sb + SM1_WH + r * 272 + c * 16, g_w1h32 + (size_t)(nh * 128 + r) * 64 + c * 4);
    }
    CP_COMMIT();
    // group 2: W1-half lo plane
    for (int i = tid; i < 2048; i += 256) {
        int r = i >> 4, c = i & 15;
        cp16(sb + SM1_WL + r * 272 + c * 16, g_w1l32 + (size_t)(nh * 128 + r) * 64 + c * 4);
    }
    CP_COMMIT();

    float* b1s = (float*)(smem + SM1_VEC);
    if (tid < 128) b1s[tid] = b1[nh * 128 + tid];

    CP_WAIT1();               // X + Wh ready (Wl may still fly)
    __syncthreads();

    const int wid = tid >> 5, lane = tid & 31;
    const int wm = (wid & 1) * 64, wn = (wid >> 1) * 32;
    const uint32_t aF = sb + SM1_XF + (((uint32_t)(wm + (lane & 15))) * KP1 + ((lane >> 4) * 8)) * 2;
    const uint32_t bH = sb + SM1_WH + (((uint32_t)(wn + (lane & 7) + ((lane >> 4) * 8))) * KP1
                                        + (((lane >> 3) & 1) * 8)) * 2;
    const uint32_t bL = sb + SM1_WL + (((uint32_t)(wn + (lane & 7) + ((lane >> 4) * 8))) * KP1
                                        + (((lane >> 3) & 1) * 8)) * 2;

    float acc[4][4][4];
    #pragma unroll
    for (int i = 0; i < 4; i++)
        #pragma unroll
        for (int j = 0; j < 4; j++)
            #pragma unroll
            for (int c = 0; c < 4; c++) acc[i][j][c] = 0.0f;

    gemm_pass<8>(acc, aF, bH, KP1, KP1);   // Xf * Wh  (Wl load hidden underneath)
    CP_WAIT0();
    __syncthreads();
    gemm_pass<8>(acc, aF, bL, KP1, KP1);   // Xf * Wl

    // epilogue: bias + relu -> fp16, packed pair stores to x1 plane
    const int g = lane >> 2, tg = lane & 3;
    #pragma unroll
    for (int mi = 0; mi < 4; mi++) {
        #pragma unroll
        for (int nj = 0; nj < 4; nj++) {
            int rA = row0 + wm + mi * 16 + g;
            int colL = wn + nj * 8 + tg * 2;
            float v0 = fmaxf(acc[mi][nj][0] + b1s[colL],     0.0f);
            float v1 = fmaxf(acc[mi][nj][1] + b1s[colL + 1], 0.0f);
            float v2 = fmaxf(acc[mi][nj][2] + b1s[colL],     0.0f);
            float v3 = fmaxf(acc[mi][nj][3] + b1s[colL + 1], 0.0f);
            size_t ix = (size_t)rA * 128 + nh * 64 + (colL >> 1);
            g_x1f32[ix]           = cvt2h(v0, v1);
            g_x1f32[ix + 8 * 128] = cvt2h(v2, v3);
        }
    }
}

// ---------------- layer 2 + head fused, writes out directly ----------------
// 256 threads, 8 warps of 64x32, N-half per CTA, K chunked 4x64, 2 CTAs/SM
__global__ __launch_bounds__(256, 2)
void k_l2(const float* __restrict__ b2, float* __restrict__ out)
{
    extern __shared__ char smem[];
    const uint32_t sb = smem_u32(smem);
    const int tid  = threadIdx.x;
    const int half = blockIdx.x & 1;
    const int row0 = (blockIdx.x >> 1) * 128;

    float* b2s   = (float*)(smem + SM2_VEC);   // [128]
    float* wcs   = b2s + 128;                  // [128]
    float* stage = wcs + 128;                  // [128]
    if (tid < 128) {
        b2s[tid]   = b2[half * 128 + tid];
        wcs[tid]   = g_wc[half * 128 + tid];
        stage[tid] = 0.0f;
    }

    // group 0: X plane fp16 [128][256]
    for (int i = tid; i < 4096; i += 256) {
        int r = i >> 5, c = i & 31;
        cp16(sb + SM2_XF + r * 528 + c * 16, g_x1f32 + (size_t)(row0 + r) * 128 + c * 4);
    }
    CP_COMMIT();
    // W chunk 0 (k=0..63): hi group, lo group
    for (int i = tid; i < 1024; i += 256) {
        int r = i >> 3, c = i & 7;
        cp16(sb + SM2_WH + r * 144 + c * 16, g_w2h32 + (size_t)(half * 128 + r) * 128 + c * 4);
    }
    CP_COMMIT();
    for (int i = tid; i < 1024; i += 256) {
        int r = i >> 3, c = i & 7;
        cp16(sb + SM2_WL + r * 144 + c * 16, g_w2l32 + (size_t)(half * 128 + r) * 128 + c * 4);
    }
    CP_COMMIT();

    const int wid = tid >> 5, lane = tid & 31;
    const int wm = (wid & 1) * 64, wn = (wid >> 1) * 32;
    const int g = lane >> 2, tg = lane & 3;
    const uint32_t aF = sb + SM2_XF + (((uint32_t)(wm + (lane & 15))) * KPX + ((lane >> 4) * 8)) * 2;
    const uint32_t bH = sb + SM2_WH + (((uint32_t)(wn + (lane & 7) + ((lane >> 4) * 8))) * KPW
                                        + (((lane >> 3) & 1) * 8)) * 2;
    const uint32_t bL = sb + SM2_WL + (((uint32_t)(wn + (lane & 7) + ((lane >> 4) * 8))) * KPW
                                        + (((lane >> 3) & 1) * 8)) * 2;

    float acc[4][4][4];
    #pragma unroll
    for (int i = 0; i < 4; i++)
        #pragma unroll
        for (int j = 0; j < 4; j++)
            #pragma unroll
            for (int c = 0; c < 4; c++) acc[i][j][c] = 0.0f;

    #pragma unroll 1
    for (int kc = 0; kc < 4; kc++) {             // K chunks of 64
        const uint32_t ao = (uint32_t)kc * 128;  // 64 elems * 2B

        CP_WAIT1();                 // current Wh (and X on first iter) ready
        __syncthreads();
        gemm_pass<4>(acc, aF + ao, bH, KPX, KPW);   // Xf * Wh
        __syncthreads();            // all warps done with Wh buffer
        if (kc < 3) {               // prefetch next chunk's Wh
            for (int i = tid; i < 1024; i += 256) {
                int r = i >> 3, cc = i & 7;
                cp16(sb + SM2_WH + r * 144 + cc * 16,
                     g_w2h32 + (size_t)(half * 128 + r) * 128 + (kc + 1) * 32 + cc * 4);
            }
            CP_COMMIT();
            CP_WAIT1();             // current Wl ready (next Wh may pend)
        } else {
            CP_WAIT0();
        }
        __syncthreads();
        gemm_pass<4>(acc, aF + ao, bL, KPX, KPW);   // Xf * Wl
        __syncthreads();            // all warps done with Wl buffer
        if (kc < 3) {               // prefetch next chunk's Wl
            for (int i = tid; i < 1024; i += 256) {
                int r = i >> 3, cc = i & 7;
                cp16(sb + SM2_WL + r * 144 + cc * 16,
                     g_w2l32 + (size_t)(half * 128 + r) * 128 + (kc + 1) * 32 + cc * 4);
            }
            CP_COMMIT();
        }
    }

    // fused epilogue: bias + relu + head dot -> per-row scalar
    float rs[4][2];
    #pragma unroll
    for (int mi = 0; mi < 4; mi++) { rs[mi][0] = 0.0f; rs[mi][1] = 0.0f; }
    #pragma unroll
    for (int mi = 0; mi < 4; mi++) {
        #pragma unroll
        for (int nj = 0; nj < 4; nj++) {
            int n0 = wn + nj * 8 + tg * 2;
            float w0 = wcs[n0], w1 = wcs[n0 + 1];
            float bb0 = b2s[n0], bb1 = b2s[n0 + 1];
            rs[mi][0] += fmaxf(acc[mi][nj][0] + bb0, 0.0f) * w0
                       + fmaxf(acc[mi][nj][1] + bb1, 0.0f) * w1;
            rs[mi][1] += fmaxf(acc[mi][nj][2] + bb0, 0.0f) * w0
                       + fmaxf(acc[mi][nj][3] + bb1, 0.0f) * w1;
        }
    }
    #pragma unroll
    for (int mi = 0; mi < 4; mi++) {
        #pragma unroll
        for (int rb = 0; rb < 2; rb++) {
            float s = rs[mi][rb];
            s += __shfl_xor_sync(0xFFFFFFFFu, s, 1);
            s += __shfl_xor_sync(0xFFFFFFFFu, s, 2);
            if (tg == 0) atomicAdd(&stage[wm + mi * 16 + g + rb * 8], s);
        }
    }
    __syncthreads();
    // both N-halves accumulate into out[row] (out zeroed by k_prep)
    if (tid < 128) atomicAdd(&out[row0 + tid], stage[tid] + 0.5f * g_bc);
}

// ---------------- launch ----------------
extern "C" void kernel_launch(void* const* d_in, const int* in_sizes, int n_in,
                              void* d_out, int out_size) {
    const float* state  = (const float*)d_in[0];
    const float* action = (const float*)d_in[1];
    const float* alphas = (const float*)d_in[2];
    const float* W1     = (const float*)d_in[3];
    const float* b1     = (const float*)d_in[4];
    const float* W2     = (const float*)d_in[5];
    const float* b2     = (const float*)d_in[6];
    const float* Wh     = (const float*)d_in[7];
    const float* bh     = (const float*)d_in[8];
    float* out = (float*)d_out;

    cudaFuncSetAttribute(k_l1, cudaFuncAttributeMaxDynamicSharedMemorySize, SMEM_L1);
    cudaFuncSetAttribute(k_l2, cudaFuncAttributeMaxDynamicSharedMemorySize, SMEM_L2);

    k_prep<<<4544, 256>>>(W1, W2, alphas, Wh, bh, state, action, out);
    k_l1<<<1024, 256, SMEM_L1>>>(b1);
    k_l2<<<1024, 256, SMEM_L2>>>(b2, out);
}

// round 17
// speedup vs baseline: 1.3446x; 1.0200x over previous
#include <cuda_runtime.h>
#include <cuda_fp16.h>
#include <cstdint>
#include <cstddef>

// ---------------- problem constants ----------------
#define NB      65536

// padded k-strides (fp16 elems)
#define KP1 136                // k=128 tiles (rows 272B)
#define KPX 264                // l2 X tile k=256 (rows 528B)
#define KPW 72                 // l2 W chunk k=64 (rows 144B)

// ---------------- smem layout (union of both roles; 106496 B -> 2 CTAs/SM) ----------------
#define SM1_VEC 0
#define SM1_XF  1024
#define SM1_WH  (SM1_XF + 34816)
#define SM1_WL  (SM1_WH + 34816)

#define SM2_VEC 0
#define SM2_XF  2048
#define SM2_WH  (SM2_XF + 67584)
#define SM2_WL  (SM2_WH + 18432)
#define SMEM_FUSED (SM2_WL + 18432)            // 106496 B

// ---------------- device scratch ----------------
__device__ __align__(16) uint32_t g_xf32[(size_t)NB * 64];    // X fp16 [B][128]
__device__ __align__(16) uint32_t g_x1f32[(size_t)NB * 128];  // x1 fp16 [B][256]
__device__ __align__(16) uint32_t g_w1h32[256 * 64];
__device__ __align__(16) uint32_t g_w1l32[256 * 64];
__device__ __align__(16) uint32_t g_w2h32[256 * 128];
__device__ __align__(16) uint32_t g_w2l32[256 * 128];
__device__ float g_wc[256];
__device__ float g_bc;
__device__ int   g_flag[512];                  // per-row-tile x1 readiness (0..2)

// ---------------- PTX helpers ----------------
__device__ __forceinline__ uint32_t smem_u32(const void* p) {
    uint32_t a;
    asm("{ .reg .u64 t; cvta.to.shared.u64 t, %1; cvt.u32.u64 %0, t; }" : "=r"(a) : "l"(p));
    return a;
}
__device__ __forceinline__ void cp16(uint32_t dst, const void* src) {
    asm volatile("cp.async.cg.shared.global [%0], [%1], 16;" :: "r"(dst), "l"(src));
}
#define CP_COMMIT() asm volatile("cp.async.commit_group;")
#define CP_WAIT0()  asm volatile("cp.async.wait_group 0;" ::: "memory")
#define CP_WAIT1()  asm volatile("cp.async.wait_group 1;" ::: "memory")

__device__ __forceinline__ void ldsm4(uint32_t* r, uint32_t addr) {
    asm volatile("ldmatrix.sync.aligned.m8n8.x4.shared.b16 {%0,%1,%2,%3}, [%4];"
        : "=r"(r[0]), "=r"(r[1]), "=r"(r[2]), "=r"(r[3]) : "r"(addr));
}
__device__ __forceinline__ void mma_f16(float* c, const uint32_t* a, const uint32_t* b) {
    asm volatile(
        "mma.sync.aligned.m16n8k16.row.col.f32.f16.f16.f32 "
        "{%0,%1,%2,%3},{%4,%5,%6,%7},{%8,%9},{%0,%1,%2,%3};"
        : "+f"(c[0]), "+f"(c[1]), "+f"(c[2]), "+f"(c[3])
        : "r"(a[0]), "r"(a[1]), "r"(a[2]), "r"(a[3]), "r"(b[0]), "r"(b[1]));
}
__device__ __forceinline__ void splitw2(float v0, float v1, uint32_t& hi, uint32_t& lo) {
    __half h0 = __float2half_rn(v0), h1 = __float2half_rn(v1);
    __half l0 = __float2half_rn(v0 - __half2float(h0));
    __half l1 = __float2half_rn(v1 - __half2float(h1));
    hi = (uint32_t)__half_as_ushort(h0) | ((uint32_t)__half_as_ushort(h1) << 16);
    lo = (uint32_t)__half_as_ushort(l0) | ((uint32_t)__half_as_ushort(l1) << 16);
}
__device__ __forceinline__ uint32_t cvt2h(float v0, float v1) {
    __half2 h = __floats2half2_rn(v0, v1);
    return *reinterpret_cast<uint32_t*>(&h);
}

// one pass over KS k-steps: warp tile 64x32 -> 4 A-ldsm + 2 B-ldsm + 16 mma per step
template<int KS>
__device__ __forceinline__ void gemm_pass(float acc[4][4][4], uint32_t Ab, uint32_t Bb,
                                          int kpA, int kpW) {
    #pragma unroll
    for (int ks = 0; ks < KS; ks++) {
        uint32_t a[4][4], b[2][4];
        #pragma unroll
        for (int mi = 0; mi < 4; mi++) ldsm4(a[mi], Ab + (mi * 16 * kpA + ks * 16) * 2);
        ldsm4(b[0], Bb + (ks * 16) * 2);
        ldsm4(b[1], Bb + (16 * kpW + ks * 16) * 2);
        #pragma unroll
        for (int mi = 0; mi < 4; mi++) {
            mma_f16(acc[mi][0], a[mi], &b[0][0]);
            mma_f16(acc[mi][1], a[mi], &b[0][2]);
            mma_f16(acc[mi][2], a[mi], &b[1][0]);
            mma_f16(acc[mi][3], a[mi], &b[1][2]);
        }
    }
}

// ---------------- unified prep: W splits + head collapse + X convert + zero out/flags ----------------
__global__ void k_prep(const float* __restrict__ W1, const float* __restrict__ W2,
                       const float* __restrict__ alphas, const float* __restrict__ Wh,
                       const float* __restrict__ bh,
                       const float* __restrict__ state, const float* __restrict__ action,
                       float* __restrict__ out) {
    const int bid = blockIdx.x, tid = threadIdx.x;
    if (bid < 64) {                       // W1 split
        int i = bid * 256 + tid;
        int row = i >> 6, kp = i & 63;
        splitw2(W1[row * 128 + kp * 2], W1[row * 128 + kp * 2 + 1], g_w1h32[i], g_w1l32[i]);
    } else if (bid < 192) {               // W2 split
        int j = (bid - 64) * 256 + tid;
        int row = j >> 7, kp = j & 127;
        splitw2(W2[row * 256 + kp * 2], W2[row * 256 + kp * 2 + 1], g_w2h32[j], g_w2l32[j]);
    } else if (bid < 448) {               // head collapse (one k per block)
        __shared__ float red[256];
        const int k = bid - 192;
        red[tid] = (tid < 200) ? alphas[tid] * Wh[tid * 256 + k] : 0.0f;
        __syncthreads();
        #pragma unroll
        for (int s = 128; s > 0; s >>= 1) {
            if (tid < s) red[tid] += red[tid + s];
            __syncthreads();
        }
        if (tid == 0) g_wc[k] = red[0];
        if (k == 0) {
            __syncthreads();
            red[tid] = (tid < 200) ? alphas[tid] * bh[tid] : 0.0f;
            __syncthreads();
            #pragma unroll
            for (int s = 128; s > 0; s >>= 1) {
                if (tid < s) red[tid] += red[tid + s];
                __syncthreads();
            }
            if (tid == 0) g_bc = red[0];
        }
    } else {                              // X convert + zero out + zero flags
        int gid = (bid - 448) * 256 + tid;
        if (gid < NB) out[gid] = 0.0f;
        if (gid < 512) g_flag[gid] = 0;
        int b  = gid >> 4;
        int kq = gid & 15;
        const float* src = (kq < 12) ? state + (size_t)b * 96 + kq * 8
                                     : action + (size_t)b * 32 + (kq - 12) * 8;
        float4 v0 = *(const float4*)src;
        float4 v1 = *(const float4*)(src + 4);
        uint4 o;
        o.x = cvt2h(v0.x, v0.y);  o.y = cvt2h(v0.z, v0.w);
        o.z = cvt2h(v1.x, v1.y);  o.w = cvt2h(v1.z, v1.w);
        *(uint4*)(g_xf32 + (size_t)b * 64 + kq * 4) = o;
    }
}

// ---------------- fused GEMM kernel: bids 0..1023 layer1, 1024..2047 layer2+head ----------------
__global__ __launch_bounds__(256, 2)
void k_fused(const float* __restrict__ b1, const float* __restrict__ b2,
             float* __restrict__ out)
{
    extern __shared__ char smem[];
    const uint32_t sb = smem_u32(smem);
    const int tid = threadIdx.x;
    const int bid = blockIdx.x;
    const int wid = tid >> 5, lane = tid & 31;
    const int wm = (wid & 1) * 64, wn = (wid >> 1) * 32;
    const int g = lane >> 2, tg = lane & 3;

    if (bid < 1024) {
        // ============ LAYER 1 role ============
        const int nh  = bid & 1;
        const int row0 = (bid >> 1) * 128;
        const int t = bid >> 1;

        for (int i = tid; i < 2048; i += 256) {
            int r = i >> 4, c = i & 15;
            cp16(sb + SM1_XF + r * 272 + c * 16, g_xf32 + (size_t)(row0 + r) * 64 + c * 4);
        }
        CP_COMMIT();
        for (int i = tid; i < 2048; i += 256) {
            int r = i >> 4, c = i & 15;
            cp16(sb + SM1_WH + r * 272 + c * 16, g_w1h32 + (size_t)(nh * 128 + r) * 64 + c * 4);
        }
        CP_COMMIT();
        for (int i = tid; i < 2048; i += 256) {
            int r = i >> 4, c = i & 15;
            cp16(sb + SM1_WL + r * 272 + c * 16, g_w1l32 + (size_t)(nh * 128 + r) * 64 + c * 4);
        }
        CP_COMMIT();

        float* b1s = (float*)(smem + SM1_VEC);
        if (tid < 128) b1s[tid] = b1[nh * 128 + tid];

        CP_WAIT1();
        __syncthreads();

        const uint32_t aF = sb + SM1_XF + (((uint32_t)(wm + (lane & 15))) * KP1 + ((lane >> 4) * 8)) * 2;
        const uint32_t bH = sb + SM1_WH + (((uint32_t)(wn + (lane & 7) + ((lane >> 4) * 8))) * KP1
                                            + (((lane >> 3) & 1) * 8)) * 2;
        const uint32_t bL = sb + SM1_WL + (((uint32_t)(wn + (lane & 7) + ((lane >> 4) * 8))) * KP1
                                            + (((lane >> 3) & 1) * 8)) * 2;

        float acc[4][4][4];
        #pragma unroll
        for (int i = 0; i < 4; i++)
            #pragma unroll
            for (int j = 0; j < 4; j++)
                #pragma unroll
                for (int c = 0; c < 4; c++) acc[i][j][c] = 0.0f;

        gemm_pass<8>(acc, aF, bH, KP1, KP1);
        CP_WAIT0();
        __syncthreads();
        gemm_pass<8>(acc, aF, bL, KP1, KP1);

        #pragma unroll
        for (int mi = 0; mi < 4; mi++) {
            #pragma unroll
            for (int nj = 0; nj < 4; nj++) {
                int rA = row0 + wm + mi * 16 + g;
                int colL = wn + nj * 8 + tg * 2;
                float v0 = fmaxf(acc[mi][nj][0] + b1s[colL],     0.0f);
                float v1 = fmaxf(acc[mi][nj][1] + b1s[colL + 1], 0.0f);
                float v2 = fmaxf(acc[mi][nj][2] + b1s[colL],     0.0f);
                float v3 = fmaxf(acc[mi][nj][3] + b1s[colL + 1], 0.0f);
                size_t ix = (size_t)rA * 128 + nh * 64 + (colL >> 1);
                g_x1f32[ix]           = cvt2h(v0, v1);
                g_x1f32[ix + 8 * 128] = cvt2h(v2, v3);
            }
        }

        // publish: make x1 stores visible, then bump tile flag
        __syncthreads();
        __threadfence();
        if (tid == 0) atomicAdd(&g_flag[t], 1);

    } else {
        // ============ LAYER 2 + head role (flag-gated) ============
        const int b2id = bid - 1024;
        const int half = b2id & 1;
        const int t    = b2id >> 1;
        const int row0 = t * 128;

        // gate: wait until both producer CTAs published this tile's x1
        if (tid == 0) {
            volatile int* f = (volatile int*)&g_flag[t];
            unsigned ns = 64;
            while (*f < 2) {
                __nanosleep(ns);
                if (ns < 2048) ns <<= 1;
            }
        }
        __syncthreads();
        __threadfence();   // acquire side: order subsequent reads after flag observation

        float* b2s   = (float*)(smem + SM2_VEC);
        float* wcs   = b2s + 128;
        float* stage = wcs + 128;
        if (tid < 128) {
            b2s[tid]   = b2[half * 128 + tid];
            wcs[tid]   = g_wc[half * 128 + tid];
            stage[tid] = 0.0f;
        }

        for (int i = tid; i < 4096; i += 256) {
            int r = i >> 5, c = i & 31;
            cp16(sb + SM2_XF + r * 528 + c * 16, g_x1f32 + (size_t)(row0 + r) * 128 + c * 4);
        }
        CP_COMMIT();
        for (int i = tid; i < 1024; i += 256) {
            int r = i >> 3, c = i & 7;
            cp16(sb + SM2_WH + r * 144 + c * 16, g_w2h32 + (size_t)(half * 128 + r) * 128 + c * 4);
        }
        CP_COMMIT();
        for (int i = tid; i < 1024; i += 256) {
            int r = i >> 3, c = i & 7;
            cp16(sb + SM2_WL + r * 144 + c * 16, g_w2l32 + (size_t)(half * 128 + r) * 128 + c * 4);
        }
        CP_COMMIT();

        const uint32_t aF = sb + SM2_XF + (((uint32_t)(wm + (lane & 15))) * KPX + ((lane >> 4) * 8)) * 2;
        const uint32_t bH = sb + SM2_WH + (((uint32_t)(wn + (lane & 7) + ((lane >> 4) * 8))) * KPW
                                            + (((lane >> 3) & 1) * 8)) * 2;
        const uint32_t bL = sb + SM2_WL + (((uint32_t)(wn + (lane & 7) + ((lane >> 4) * 8))) * KPW
                                            + (((lane >> 3) & 1) * 8)) * 2;

        float acc[4][4][4];
        #pragma unroll
        for (int i = 0; i < 4; i++)
            #pragma unroll
            for (int j = 0; j < 4; j++)
                #pragma unroll
                for (int c = 0; c < 4; c++) acc[i][j][c] = 0.0f;

        #pragma unroll 1
        for (int kc = 0; kc < 4; kc++) {
            const uint32_t ao = (uint32_t)kc * 128;

            CP_WAIT1();
            __syncthreads();
            gemm_pass<4>(acc, aF + ao, bH, KPX, KPW);
            __syncthreads();
            if (kc < 3) {
                for (int i = tid; i < 1024; i += 256) {
                    int r = i >> 3, cc = i & 7;
                    cp16(sb + SM2_WH + r * 144 + cc * 16,
                         g_w2h32 + (size_t)(half * 128 + r) * 128 + (kc + 1) * 32 + cc * 4);
                }
                CP_COMMIT();
                CP_WAIT1();
            } else {
                CP_WAIT0();
            }
            __syncthreads();
            gemm_pass<4>(acc, aF + ao, bL, KPX, KPW);
            __syncthreads();
            if (kc < 3) {
                for (int i = tid; i < 1024; i += 256) {
                    int r = i >> 3, cc = i & 7;
                    cp16(sb + SM2_WL + r * 144 + cc * 16,
                         g_w2l32 + (size_t)(half * 128 + r) * 128 + (kc + 1) * 32 + cc * 4);
                }
                CP_COMMIT();
            }
        }

        float rs[4][2];
        #pragma unroll
        for (int mi = 0; mi < 4; mi++) { rs[mi][0] = 0.0f; rs[mi][1] = 0.0f; }
        #pragma unroll
        for (int mi = 0; mi < 4; mi++) {
            #pragma unroll
            for (int nj = 0; nj < 4; nj++) {
                int n0 = wn + nj * 8 + tg * 2;
                float w0 = wcs[n0], w1 = wcs[n0 + 1];
                float bb0 = b2s[n0], bb1 = b2s[n0 + 1];
                rs[mi][0] += fmaxf(acc[mi][nj][0] + bb0, 0.0f) * w0
                           + fmaxf(acc[mi][nj][1] + bb1, 0.0f) * w1;
                rs[mi][1] += fmaxf(acc[mi][nj][2] + bb0, 0.0f) * w0
                           + fmaxf(acc[mi][nj][3] + bb1, 0.0f) * w1;
            }
        }
        #pragma unroll
        for (int mi = 0; mi < 4; mi++) {
            #pragma unroll
            for (int rb = 0; rb < 2; rb++) {
                float s = rs[mi][rb];
                s += __shfl_xor_sync(0xFFFFFFFFu, s, 1);
                s += __shfl_xor_sync(0xFFFFFFFFu, s, 2);
                if (tg == 0) atomicAdd(&stage[wm + mi * 16 + g + rb * 8], s);
            }
        }
        __syncthreads();
        if (tid < 128) atomicAdd(&out[row0 + tid], stage[tid] + 0.5f * g_bc);
    }
}

// ---------------- launch ----------------
extern "C" void kernel_launch(void* const* d_in, const int* in_sizes, int n_in,
                              void* d_out, int out_size) {
    const float* state  = (const float*)d_in[0];
    const float* action = (const float*)d_in[1];
    const float* alphas = (const float*)d_in[2];
    const float* W1     = (const float*)d_in[3];
    const float* b1     = (const float*)d_in[4];
    const float* W2     = (const float*)d_in[5];
    const float* b2     = (const float*)d_in[6];
    const float* Wh     = (const float*)d_in[7];
    const float* bh     = (const float*)d_in[8];
    float* out = (float*)d_out;

    cudaFuncSetAttribute(k_fused, cudaFuncAttributeMaxDynamicSharedMemorySize, SMEM_FUSED);

    k_prep<<<4544, 256>>>(W1, W2, alphas, Wh, bh, state, action, out);
    k_fused<<<2048, 256, SMEM_FUSED>>>(b1, b2, out);
}